// round 8
// baseline (speedup 1.0000x reference)
#include <cuda_runtime.h>
#include <cuda_fp16.h>
#include <cstdint>

// Problem shapes (fixed)
#define B_  8
#define C_  64
#define N_  2000
#define T_  12
#define E_  64000
#define HID_ 32

// Quarter-blocked fp16 tables:
// g_T[b][q][tab][n][16 halves], tab 0 = A (includes conv_b), tab 1 = Bv.
// One (b,q) pair = 2 x 64KB contiguous slices -> L1-resident in gather.
// uint2 units: row stride 4, one table slice = N_*4 = 8000, (b,q) block = 16000.
__device__ __half g_T[B_ * 4 * 2 * N_ * 16];

__device__ __forceinline__ unsigned pack_half2(float a, float b) {
    __half2 h = __floats2half2_rn(a, b);
    return *reinterpret_cast<unsigned*>(&h);
}

// ---------------------------------------------------------------------------
// Stage kernel (fold eliminated via two-step GEMM):
//   slt/srt : time reduction of x                      (phase 1)
//   u = slt @ (s1*W3),  v = srt @ (s2*W4)              (phase 2a, 64x32)
//   A = u @ cw[:, :32]^T + cb,  Bv = v @ cw[:, 32:]^T   (phase 2b, 64x64)
// 64-n tile per block, 256 threads, 80 KB dynamic smem.
// ---------------------------------------------------------------------------
__global__ __launch_bounds__(256) void stage_AB_kernel(const float* __restrict__ x,
                                                       const float* __restrict__ W3,
                                                       const float* __restrict__ W4,
                                                       const float* __restrict__ cw,
                                                       const float* __restrict__ s1p,
                                                       const float* __restrict__ s2p,
                                                       const float* __restrict__ conv_b) {
    extern __shared__ float4 sm[];
    float4* sW3    = sm;            // [c][h4]   64*8  = 512 f4
    float4* sW4    = sm + 512;      // 512 f4
    float4* slt4   = sm + 1024;     // [c][n4]   64*16 = 1024 f4
    float4* srt4   = sm + 2048;     // 1024 f4
    float4* scwT1  = sm + 3072;     // [h][co4]  32*16 = 512 f4
    float4* scwT2  = sm + 3584;     // 512 f4
    float4* su4    = sm + 4096;     // [h][n4]   32*16 = 512 f4
    float4* sv4    = sm + 4608;     // 512 f4
    float* slt = reinterpret_cast<float*>(slt4);
    float* srt = reinterpret_cast<float*>(srt4);
    float* scwT1f = reinterpret_cast<float*>(scwT1);
    float* scwT2f = reinterpret_cast<float*>(scwT2);

    const int tid = threadIdx.x;
    const int b = blockIdx.y;
    const int n0 = blockIdx.x * 64;

    const float s1 = __ldg(s1p);
    const float s2 = __ldg(s2p);

    // Stage scaled W3/W4 (each 512 f4)
    const float4* W3_4 = reinterpret_cast<const float4*>(W3);
    const float4* W4_4 = reinterpret_cast<const float4*>(W4);
#pragma unroll
    for (int k = 0; k < 2; k++) {
        int i = tid + 256 * k;
        float4 w3 = W3_4[i], w4 = W4_4[i];
        sW3[i] = make_float4(w3.x * s1, w3.y * s1, w3.z * s1, w3.w * s1);
        sW4[i] = make_float4(w4.x * s2, w4.y * s2, w4.z * s2, w4.w * s2);
    }

    // Stage cw transposed: scwT1[h][co] = cw[co][h], scwT2[h][co] = cw[co][32+h]
#pragma unroll
    for (int k = 0; k < 16; k++) {
        int id = tid + 256 * k;     // 0..4095
        int co = id & 63;
        int hh = id >> 6;           // 0..63
        float vv = __ldg(cw + co * 64 + hh);
        if (hh < 32) scwT1f[hh * 64 + co] = vv;
        else         scwT2f[(hh - 32) * 64 + co] = vv;
    }

    // Phase 1: time reduction. 64c x 64n pairs, 16 per thread.
#pragma unroll
    for (int k = 0; k < 16; k++) {
        int p = tid + 256 * k;
        int c = p >> 6;
        int nl = p & 63;
        int n = n0 + nl;
        float lt = 0.f, s = 0.f;
        if (n < N_) {
            const float4* px = reinterpret_cast<const float4*>(
                x + ((size_t)(b * C_ + c) * N_ + n) * T_);
            float4 v0 = px[0], v1 = px[1], v2 = px[2];
            float xv[12] = {v0.x, v0.y, v0.z, v0.w,
                            v1.x, v1.y, v1.z, v1.w,
                            v2.x, v2.y, v2.z, v2.w};
#pragma unroll
            for (int t = 0; t < T_; t++) {
                lt = fmaf(xv[t], (float)t * (1.0f / 11.0f), lt);
                s += xv[t];
            }
        }
        slt[c * 64 + nl] = lt;
        srt[c * 64 + nl] = s - lt;    // t_dn = 1 - t_up
    }
    __syncthreads();

    // Phase 2a: u[h][n] = sum_c slt[c][n]*sW3[c][h]  (threads 0..127)
    //           v[h][n] = sum_c srt[c][n]*sW4[c][h]  (threads 128..255)
    {
        const int t = tid & 127;
        const int ng2 = t & 15;       // n4 group
        const int hg = t >> 4;        // 0..7 (h4 group)
        const float4* src = (tid < 128) ? slt4 : srt4;
        const float4* wsm = (tid < 128) ? sW3 : sW4;
        float4* dst = (tid < 128) ? su4 : sv4;

        float4 acc0 = {0,0,0,0}, acc1 = {0,0,0,0}, acc2 = {0,0,0,0}, acc3 = {0,0,0,0};
#pragma unroll 16
        for (int c = 0; c < 64; c++) {
            float4 l4 = src[c * 16 + ng2];
            float4 w = wsm[c * 8 + hg];
            acc0.x = fmaf(l4.x, w.x, acc0.x); acc0.y = fmaf(l4.y, w.x, acc0.y);
            acc0.z = fmaf(l4.z, w.x, acc0.z); acc0.w = fmaf(l4.w, w.x, acc0.w);
            acc1.x = fmaf(l4.x, w.y, acc1.x); acc1.y = fmaf(l4.y, w.y, acc1.y);
            acc1.z = fmaf(l4.z, w.y, acc1.z); acc1.w = fmaf(l4.w, w.y, acc1.w);
            acc2.x = fmaf(l4.x, w.z, acc2.x); acc2.y = fmaf(l4.y, w.z, acc2.y);
            acc2.z = fmaf(l4.z, w.z, acc2.z); acc2.w = fmaf(l4.w, w.z, acc2.w);
            acc3.x = fmaf(l4.x, w.w, acc3.x); acc3.y = fmaf(l4.y, w.w, acc3.y);
            acc3.z = fmaf(l4.z, w.w, acc3.z); acc3.w = fmaf(l4.w, w.w, acc3.w);
        }
        dst[(hg * 4 + 0) * 16 + ng2] = acc0;
        dst[(hg * 4 + 1) * 16 + ng2] = acc1;
        dst[(hg * 4 + 2) * 16 + ng2] = acc2;
        dst[(hg * 4 + 3) * 16 + ng2] = acc3;
    }
    __syncthreads();

    // Phase 2b: A[n][co] = sum_h u[h][n]*scwT1[h][co] (+cb); Bv from v, scwT2.
    const int cg = tid & 15;          // co4 group
    const int ng = tid >> 4;          // n4 group

    float4 a0 = {0,0,0,0}, a1 = {0,0,0,0}, a2 = {0,0,0,0}, a3 = {0,0,0,0};
    float4 b0 = {0,0,0,0}, b1 = {0,0,0,0}, b2 = {0,0,0,0}, b3 = {0,0,0,0};

#pragma unroll 8
    for (int h = 0; h < 32; h++) {
        float4 u4 = su4[h * 16 + ng];
        float4 v4 = sv4[h * 16 + ng];
        float4 m1 = scwT1[h * 16 + cg];
        float4 m2 = scwT2[h * 16 + cg];

        a0.x = fmaf(u4.x, m1.x, a0.x); a0.y = fmaf(u4.x, m1.y, a0.y);
        a0.z = fmaf(u4.x, m1.z, a0.z); a0.w = fmaf(u4.x, m1.w, a0.w);
        a1.x = fmaf(u4.y, m1.x, a1.x); a1.y = fmaf(u4.y, m1.y, a1.y);
        a1.z = fmaf(u4.y, m1.z, a1.z); a1.w = fmaf(u4.y, m1.w, a1.w);
        a2.x = fmaf(u4.z, m1.x, a2.x); a2.y = fmaf(u4.z, m1.y, a2.y);
        a2.z = fmaf(u4.z, m1.z, a2.z); a2.w = fmaf(u4.z, m1.w, a2.w);
        a3.x = fmaf(u4.w, m1.x, a3.x); a3.y = fmaf(u4.w, m1.y, a3.y);
        a3.z = fmaf(u4.w, m1.z, a3.z); a3.w = fmaf(u4.w, m1.w, a3.w);

        b0.x = fmaf(v4.x, m2.x, b0.x); b0.y = fmaf(v4.x, m2.y, b0.y);
        b0.z = fmaf(v4.x, m2.z, b0.z); b0.w = fmaf(v4.x, m2.w, b0.w);
        b1.x = fmaf(v4.y, m2.x, b1.x); b1.y = fmaf(v4.y, m2.y, b1.y);
        b1.z = fmaf(v4.y, m2.z, b1.z); b1.w = fmaf(v4.y, m2.w, b1.w);
        b2.x = fmaf(v4.z, m2.x, b2.x); b2.y = fmaf(v4.z, m2.y, b2.y);
        b2.z = fmaf(v4.z, m2.z, b2.z); b2.w = fmaf(v4.z, m2.w, b2.w);
        b3.x = fmaf(v4.w, m2.x, b3.x); b3.y = fmaf(v4.w, m2.y, b3.y);
        b3.z = fmaf(v4.w, m2.z, b3.z); b3.w = fmaf(v4.w, m2.w, b3.w);
    }

    float4 cbv = reinterpret_cast<const float4*>(conv_b)[cg];
    uint2* gT = reinterpret_cast<uint2*>(g_T);

    // Blocked table indexing: quarter q = cg>>2, sub-slot = cg&3.
    const int q = cg >> 2;
    const int sub = cg & 3;
    const size_t basebq = ((size_t)(b * 4 + q)) * (2 * N_ * 4);   // uint2 units

    float4 av[4] = {a0, a1, a2, a3};
    float4 bv[4] = {b0, b1, b2, b3};
#pragma unroll
    for (int i = 0; i < 4; i++) {
        int n = n0 + ng * 4 + i;
        if (n < N_) {
            float4 aa = av[i];
            aa.x += cbv.x; aa.y += cbv.y; aa.z += cbv.z; aa.w += cbv.w;
            uint2 ua, ub;
            ua.x = pack_half2(aa.x, aa.y);
            ua.y = pack_half2(aa.z, aa.w);
            ub.x = pack_half2(bv[i].x, bv[i].y);
            ub.y = pack_half2(bv[i].z, bv[i].w);
            gT[basebq + (size_t)n * 4 + sub] = ua;                 // A slice
            gT[basebq + (size_t)(N_ + n) * 4 + sub] = ub;          // B slice
        }
    }
}

// ---------------------------------------------------------------------------
// Gather kernel: out[b,e,c] = A[b,idx[e],c] + Bv[b,idy[e],c]
// Grid (E/64, 4 quarters, B). Per (b,q) the A+B slices are 128 KB contiguous
// -> L1-resident. 4 threads/edge: 8B gathered loads (full sectors),
// 16B coalesced stores.
// ---------------------------------------------------------------------------
__global__ __launch_bounds__(256) void gather_add_kernel(const int* __restrict__ idx,
                                                         const int* __restrict__ idy,
                                                         float4* __restrict__ out) {
    const int tid = threadIdx.x;
    const int q = blockIdx.y;         // 0..3
    const int b = blockIdx.z;         // 0..7
    const int el = tid >> 2;          // 0..63
    const int sub = tid & 3;          // uint2 within 32B quarter-row
    const int e = blockIdx.x * 64 + el;

    const int n1 = __ldg(idx + e);
    const int n2 = __ldg(idy + e);

    const uint2* __restrict__ base =
        reinterpret_cast<const uint2*>(g_T) + ((size_t)(b * 4 + q)) * (2 * N_ * 4);

    uint2 ua = __ldg(base + (size_t)n1 * 4 + sub);
    uint2 ub = __ldg(base + (size_t)(N_ + n2) * 4 + sub);

    float2 a0 = __half22float2(*reinterpret_cast<__half2*>(&ua.x));
    float2 a1 = __half22float2(*reinterpret_cast<__half2*>(&ua.y));
    float2 v0 = __half22float2(*reinterpret_cast<__half2*>(&ub.x));
    float2 v1 = __half22float2(*reinterpret_cast<__half2*>(&ub.y));

    out[((size_t)b * E_ + e) * 16 + q * 4 + sub] =
        make_float4(a0.x + v0.x, a0.y + v0.y, a1.x + v1.x, a1.y + v1.y);
}

// ---------------------------------------------------------------------------
// Launch. Inputs: x, idx, idy, W1_scale, W2_scale, W3, W4, conv_w, conv_b
// ---------------------------------------------------------------------------
extern "C" void kernel_launch(void* const* d_in, const int* in_sizes, int n_in,
                              void* d_out, int out_size) {
    const float* x   = (const float*)d_in[0];
    const int* idx   = (const int*)d_in[1];
    const int* idy   = (const int*)d_in[2];
    const float* s1  = (const float*)d_in[3];
    const float* s2  = (const float*)d_in[4];
    const float* W3  = (const float*)d_in[5];
    const float* W4  = (const float*)d_in[6];
    const float* cw  = (const float*)d_in[7];
    const float* cb  = (const float*)d_in[8];
    float4* out = (float4*)d_out;

    const int smem_bytes = 5120 * sizeof(float4);   // 80 KB
    cudaFuncSetAttribute(stage_AB_kernel,
                         cudaFuncAttributeMaxDynamicSharedMemorySize, smem_bytes);

    dim3 grd2((N_ + 63) / 64, B_);
    stage_AB_kernel<<<grd2, 256, smem_bytes>>>(x, W3, W4, cw, s1, s2, cb);

    dim3 grd3(E_ / 64, 4, B_);        // (1000, 4, 8) = 32000 blocks
    gather_add_kernel<<<grd3, 256>>>(idx, idy, out);
}

// round 10
// speedup vs baseline: 1.0305x; 1.0305x over previous
#include <cuda_runtime.h>
#include <cuda_fp16.h>
#include <cstdint>

// Problem shapes (fixed)
#define B_  8
#define C_  64
#define N_  2000
#define T_  12
#define E_  64000
#define HID_ 32

// fp16 tables, flat layout [b][n][64c]: one row = 128B = exactly one L1 line.
// float4 units: row stride 8.
__device__ __half g_Ah[B_ * N_ * C_];      // includes conv_b
__device__ __half g_Bh[B_ * N_ * C_];

__device__ __forceinline__ unsigned pack_half2(float a, float b) {
    __half2 h = __floats2half2_rn(a, b);
    return *reinterpret_cast<unsigned*>(&h);
}

// ---------------------------------------------------------------------------
// Stage kernel (fold eliminated via two-step GEMM):
//   slt/srt : time reduction of x                      (phase 1)
//   u = slt @ (s1*W3),  v = srt @ (s2*W4)              (phase 2a, 64x32)
//   A = u @ cw[:, :32]^T + cb,  Bv = v @ cw[:, 32:]^T   (phase 2b, 64x64)
// 64-n tile per block, 256 threads, 80 KB dynamic smem.
// ---------------------------------------------------------------------------
__global__ __launch_bounds__(256) void stage_AB_kernel(const float* __restrict__ x,
                                                       const float* __restrict__ W3,
                                                       const float* __restrict__ W4,
                                                       const float* __restrict__ cw,
                                                       const float* __restrict__ s1p,
                                                       const float* __restrict__ s2p,
                                                       const float* __restrict__ conv_b) {
    extern __shared__ float4 sm[];
    float4* sW3    = sm;            // [c][h4]   64*8  = 512 f4
    float4* sW4    = sm + 512;      // 512 f4
    float4* slt4   = sm + 1024;     // [c][n4]   64*16 = 1024 f4
    float4* srt4   = sm + 2048;     // 1024 f4
    float4* scwT1  = sm + 3072;     // [h][co4]  32*16 = 512 f4
    float4* scwT2  = sm + 3584;     // 512 f4
    float4* su4    = sm + 4096;     // [h][n4]   32*16 = 512 f4
    float4* sv4    = sm + 4608;     // 512 f4
    float* slt = reinterpret_cast<float*>(slt4);
    float* srt = reinterpret_cast<float*>(srt4);
    float* scwT1f = reinterpret_cast<float*>(scwT1);
    float* scwT2f = reinterpret_cast<float*>(scwT2);

    const int tid = threadIdx.x;
    const int b = blockIdx.y;
    const int n0 = blockIdx.x * 64;

    const float s1 = __ldg(s1p);
    const float s2 = __ldg(s2p);

    // Stage scaled W3/W4 (each 512 f4)
    const float4* W3_4 = reinterpret_cast<const float4*>(W3);
    const float4* W4_4 = reinterpret_cast<const float4*>(W4);
#pragma unroll
    for (int k = 0; k < 2; k++) {
        int i = tid + 256 * k;
        float4 w3 = W3_4[i], w4 = W4_4[i];
        sW3[i] = make_float4(w3.x * s1, w3.y * s1, w3.z * s1, w3.w * s1);
        sW4[i] = make_float4(w4.x * s2, w4.y * s2, w4.z * s2, w4.w * s2);
    }

    // Stage cw transposed: scwT1[h][co] = cw[co][h], scwT2[h][co] = cw[co][32+h]
#pragma unroll
    for (int k = 0; k < 16; k++) {
        int id = tid + 256 * k;     // 0..4095
        int co = id & 63;
        int hh = id >> 6;           // 0..63
        float vv = __ldg(cw + co * 64 + hh);
        if (hh < 32) scwT1f[hh * 64 + co] = vv;
        else         scwT2f[(hh - 32) * 64 + co] = vv;
    }

    // Phase 1: time reduction. 64c x 64n pairs, 16 per thread.
#pragma unroll
    for (int k = 0; k < 16; k++) {
        int p = tid + 256 * k;
        int c = p >> 6;
        int nl = p & 63;
        int n = n0 + nl;
        float lt = 0.f, s = 0.f;
        if (n < N_) {
            const float4* px = reinterpret_cast<const float4*>(
                x + ((size_t)(b * C_ + c) * N_ + n) * T_);
            float4 v0 = px[0], v1 = px[1], v2 = px[2];
            float xv[12] = {v0.x, v0.y, v0.z, v0.w,
                            v1.x, v1.y, v1.z, v1.w,
                            v2.x, v2.y, v2.z, v2.w};
#pragma unroll
            for (int t = 0; t < T_; t++) {
                lt = fmaf(xv[t], (float)t * (1.0f / 11.0f), lt);
                s += xv[t];
            }
        }
        slt[c * 64 + nl] = lt;
        srt[c * 64 + nl] = s - lt;    // t_dn = 1 - t_up
    }
    __syncthreads();

    // Phase 2a: u[h][n] = sum_c slt[c][n]*sW3[c][h]  (threads 0..127)
    //           v[h][n] = sum_c srt[c][n]*sW4[c][h]  (threads 128..255)
    {
        const int t = tid & 127;
        const int ng2 = t & 15;       // n4 group
        const int hg = t >> 4;        // 0..7 (h4 group)
        const float4* src = (tid < 128) ? slt4 : srt4;
        const float4* wsm = (tid < 128) ? sW3 : sW4;
        float4* dst = (tid < 128) ? su4 : sv4;

        float4 acc0 = {0,0,0,0}, acc1 = {0,0,0,0}, acc2 = {0,0,0,0}, acc3 = {0,0,0,0};
#pragma unroll 16
        for (int c = 0; c < 64; c++) {
            float4 l4 = src[c * 16 + ng2];
            float4 w = wsm[c * 8 + hg];
            acc0.x = fmaf(l4.x, w.x, acc0.x); acc0.y = fmaf(l4.y, w.x, acc0.y);
            acc0.z = fmaf(l4.z, w.x, acc0.z); acc0.w = fmaf(l4.w, w.x, acc0.w);
            acc1.x = fmaf(l4.x, w.y, acc1.x); acc1.y = fmaf(l4.y, w.y, acc1.y);
            acc1.z = fmaf(l4.z, w.y, acc1.z); acc1.w = fmaf(l4.w, w.y, acc1.w);
            acc2.x = fmaf(l4.x, w.z, acc2.x); acc2.y = fmaf(l4.y, w.z, acc2.y);
            acc2.z = fmaf(l4.z, w.z, acc2.z); acc2.w = fmaf(l4.w, w.z, acc2.w);
            acc3.x = fmaf(l4.x, w.w, acc3.x); acc3.y = fmaf(l4.y, w.w, acc3.y);
            acc3.z = fmaf(l4.z, w.w, acc3.z); acc3.w = fmaf(l4.w, w.w, acc3.w);
        }
        dst[(hg * 4 + 0) * 16 + ng2] = acc0;
        dst[(hg * 4 + 1) * 16 + ng2] = acc1;
        dst[(hg * 4 + 2) * 16 + ng2] = acc2;
        dst[(hg * 4 + 3) * 16 + ng2] = acc3;
    }
    __syncthreads();

    // Phase 2b: A[n][co] = sum_h u[h][n]*scwT1[h][co] (+cb); Bv from v, scwT2.
    const int cg = tid & 15;          // co4 group
    const int ng = tid >> 4;          // n4 group

    float4 a0 = {0,0,0,0}, a1 = {0,0,0,0}, a2 = {0,0,0,0}, a3 = {0,0,0,0};
    float4 b0 = {0,0,0,0}, b1 = {0,0,0,0}, b2 = {0,0,0,0}, b3 = {0,0,0,0};

#pragma unroll 8
    for (int h = 0; h < 32; h++) {
        float4 u4 = su4[h * 16 + ng];
        float4 v4 = sv4[h * 16 + ng];
        float4 m1 = scwT1[h * 16 + cg];
        float4 m2 = scwT2[h * 16 + cg];

        a0.x = fmaf(u4.x, m1.x, a0.x); a0.y = fmaf(u4.x, m1.y, a0.y);
        a0.z = fmaf(u4.x, m1.z, a0.z); a0.w = fmaf(u4.x, m1.w, a0.w);
        a1.x = fmaf(u4.y, m1.x, a1.x); a1.y = fmaf(u4.y, m1.y, a1.y);
        a1.z = fmaf(u4.y, m1.z, a1.z); a1.w = fmaf(u4.y, m1.w, a1.w);
        a2.x = fmaf(u4.z, m1.x, a2.x); a2.y = fmaf(u4.z, m1.y, a2.y);
        a2.z = fmaf(u4.z, m1.z, a2.z); a2.w = fmaf(u4.z, m1.w, a2.w);
        a3.x = fmaf(u4.w, m1.x, a3.x); a3.y = fmaf(u4.w, m1.y, a3.y);
        a3.z = fmaf(u4.w, m1.z, a3.z); a3.w = fmaf(u4.w, m1.w, a3.w);

        b0.x = fmaf(v4.x, m2.x, b0.x); b0.y = fmaf(v4.x, m2.y, b0.y);
        b0.z = fmaf(v4.x, m2.z, b0.z); b0.w = fmaf(v4.x, m2.w, b0.w);
        b1.x = fmaf(v4.y, m2.x, b1.x); b1.y = fmaf(v4.y, m2.y, b1.y);
        b1.z = fmaf(v4.y, m2.z, b1.z); b1.w = fmaf(v4.y, m2.w, b1.w);
        b2.x = fmaf(v4.z, m2.x, b2.x); b2.y = fmaf(v4.z, m2.y, b2.y);
        b2.z = fmaf(v4.z, m2.z, b2.z); b2.w = fmaf(v4.z, m2.w, b2.w);
        b3.x = fmaf(v4.w, m2.x, b3.x); b3.y = fmaf(v4.w, m2.y, b3.y);
        b3.z = fmaf(v4.w, m2.z, b3.z); b3.w = fmaf(v4.w, m2.w, b3.w);
    }

    float4 cbv = reinterpret_cast<const float4*>(conv_b)[cg];
    uint2* gA2 = reinterpret_cast<uint2*>(g_Ah);
    uint2* gB2 = reinterpret_cast<uint2*>(g_Bh);

    float4 av[4] = {a0, a1, a2, a3};
    float4 bv[4] = {b0, b1, b2, b3};
#pragma unroll
    for (int i = 0; i < 4; i++) {
        int n = n0 + ng * 4 + i;
        if (n < N_) {
            size_t o = ((size_t)b * N_ + n) * 16 + cg;
            float4 aa = av[i];
            aa.x += cbv.x; aa.y += cbv.y; aa.z += cbv.z; aa.w += cbv.w;
            uint2 ua, ub;
            ua.x = pack_half2(aa.x, aa.y);
            ua.y = pack_half2(aa.z, aa.w);
            ub.x = pack_half2(bv[i].x, bv[i].y);
            ub.y = pack_half2(bv[i].z, bv[i].w);
            gA2[o] = ua;
            gB2[o] = ub;
        }
    }
}

// ---------------------------------------------------------------------------
// Gather kernel: out[b,e,c] = A[b,idx[e],c] + Bv[b,idy[e],c]
// 8 threads/edge, each loading ONE float4 (16B) per table; the warp's single
// LDG.128 touches exactly 1 line per edge per table (the wavefront minimum).
// Grid (E/32, B) x 256 threads = 16000 blocks.
// ---------------------------------------------------------------------------
__global__ __launch_bounds__(256) void gather_add_kernel(const int* __restrict__ idx,
                                                         const int* __restrict__ idy,
                                                         float4* __restrict__ out) {
    const int tid = threadIdx.x;
    const int b = blockIdx.y;
    const int el = tid >> 3;          // 0..31
    const int q = tid & 7;            // float4 (8 halves) within the 128B row
    const int e = blockIdx.x * 32 + el;

    const int n1 = __ldg(idx + e);
    const int n2 = __ldg(idy + e);

    const float4* __restrict__ A4 = reinterpret_cast<const float4*>(g_Ah);
    const float4* __restrict__ B4 = reinterpret_cast<const float4*>(g_Bh);

    float4 ua = __ldg(A4 + ((size_t)b * N_ + n1) * 8 + q);
    float4 ub = __ldg(B4 + ((size_t)b * N_ + n2) * 8 + q);

    const __half2* ha = reinterpret_cast<const __half2*>(&ua);
    const __half2* hb = reinterpret_cast<const __half2*>(&ub);

    float2 r0a = __half22float2(ha[0]), r0b = __half22float2(hb[0]);
    float2 r1a = __half22float2(ha[1]), r1b = __half22float2(hb[1]);
    float2 r2a = __half22float2(ha[2]), r2b = __half22float2(hb[2]);
    float2 r3a = __half22float2(ha[3]), r3b = __half22float2(hb[3]);

    size_t o = ((size_t)b * E_ + e) * 16 + q * 2;
    out[o]     = make_float4(r0a.x + r0b.x, r0a.y + r0b.y, r1a.x + r1b.x, r1a.y + r1b.y);
    out[o + 1] = make_float4(r2a.x + r2b.x, r2a.y + r2b.y, r3a.x + r3b.x, r3a.y + r3b.y);
}

// ---------------------------------------------------------------------------
// Launch. Inputs: x, idx, idy, W1_scale, W2_scale, W3, W4, conv_w, conv_b
// ---------------------------------------------------------------------------
extern "C" void kernel_launch(void* const* d_in, const int* in_sizes, int n_in,
                              void* d_out, int out_size) {
    const float* x   = (const float*)d_in[0];
    const int* idx   = (const int*)d_in[1];
    const int* idy   = (const int*)d_in[2];
    const float* s1  = (const float*)d_in[3];
    const float* s2  = (const float*)d_in[4];
    const float* W3  = (const float*)d_in[5];
    const float* W4  = (const float*)d_in[6];
    const float* cw  = (const float*)d_in[7];
    const float* cb  = (const float*)d_in[8];
    float4* out = (float4*)d_out;

    const int smem_bytes = 5120 * sizeof(float4);   // 80 KB
    cudaFuncSetAttribute(stage_AB_kernel,
                         cudaFuncAttributeMaxDynamicSharedMemorySize, smem_bytes);

    dim3 grd2((N_ + 63) / 64, B_);
    stage_AB_kernel<<<grd2, 256, smem_bytes>>>(x, W3, W4, cw, s1, s2, cb);

    dim3 grd3(E_ / 32, B_);           // (2000, 8) = 16000 blocks
    gather_add_kernel<<<grd3, 256>>>(idx, idy, out);
}

// round 11
// speedup vs baseline: 1.2223x; 1.1861x over previous
#include <cuda_runtime.h>
#include <cuda_fp16.h>
#include <cstdint>

// Problem shapes (fixed)
#define B_  8
#define C_  64
#define N_  2000
#define T_  12
#define E_  64000
#define HID_ 32

// fp16 tables, flat layout [b][n][64c]: one row = 128B = one L1 line.
// uint2 units: row stride 16.
__device__ __half g_Ah[B_ * N_ * C_];      // includes conv_b
__device__ __half g_Bh[B_ * N_ * C_];

__device__ __forceinline__ unsigned pack_half2(float a, float b) {
    __half2 h = __floats2half2_rn(a, b);
    return *reinterpret_cast<unsigned*>(&h);
}

// ---------------------------------------------------------------------------
// Stage kernel, 512 threads/block (2x R7 parallelism per block):
//   phase 1 : time reduction of x -> slt/srt
//   phase 2a: u = slt @ (s1*W3), v = srt @ (s2*W4)     (64x32 each)
//   phase 2b: A = u @ cw[:,:32]^T + cb, Bv = v @ cw[:,32:]^T
// 64-n tile per block, 80 KB dynamic smem.
// ---------------------------------------------------------------------------
__global__ __launch_bounds__(512) void stage_AB_kernel(const float* __restrict__ x,
                                                       const float* __restrict__ W3,
                                                       const float* __restrict__ W4,
                                                       const float* __restrict__ cw,
                                                       const float* __restrict__ s1p,
                                                       const float* __restrict__ s2p,
                                                       const float* __restrict__ conv_b) {
    extern __shared__ float4 sm[];
    float4* sW3    = sm;            // [c][h4]   64*8  = 512 f4
    float4* sW4    = sm + 512;      // 512 f4
    float4* slt4   = sm + 1024;     // [c][n4]   64*16 = 1024 f4
    float4* srt4   = sm + 2048;     // 1024 f4
    float4* scwT1  = sm + 3072;     // [h][co4]  32*16 = 512 f4
    float4* scwT2  = sm + 3584;     // 512 f4
    float4* su4    = sm + 4096;     // [h][n4]   32*16 = 512 f4
    float4* sv4    = sm + 4608;     // 512 f4
    float* slt = reinterpret_cast<float*>(slt4);
    float* srt = reinterpret_cast<float*>(srt4);
    float* scwT1f = reinterpret_cast<float*>(scwT1);
    float* scwT2f = reinterpret_cast<float*>(scwT2);

    const int tid = threadIdx.x;
    const int b = blockIdx.y;
    const int n0 = blockIdx.x * 64;

    const float s1 = __ldg(s1p);
    const float s2 = __ldg(s2p);

    // Stage scaled W3/W4 (512 f4 each) — one pass with 512 threads
    {
        const float4* W3_4 = reinterpret_cast<const float4*>(W3);
        const float4* W4_4 = reinterpret_cast<const float4*>(W4);
        float4 w3 = W3_4[tid], w4 = W4_4[tid];
        sW3[tid] = make_float4(w3.x * s1, w3.y * s1, w3.z * s1, w3.w * s1);
        sW4[tid] = make_float4(w4.x * s2, w4.y * s2, w4.z * s2, w4.w * s2);
    }

    // Stage cw transposed: scwT1[h][co] = cw[co][h], scwT2[h][co] = cw[co][32+h]
#pragma unroll
    for (int k = 0; k < 8; k++) {
        int id = tid + 512 * k;     // 0..4095
        int co = id & 63;
        int hh = id >> 6;           // 0..63
        float vv = __ldg(cw + co * 64 + hh);
        if (hh < 32) scwT1f[hh * 64 + co] = vv;
        else         scwT2f[(hh - 32) * 64 + co] = vv;
    }

    // Phase 1: time reduction. 64c x 64n pairs, 8 per thread.
#pragma unroll
    for (int k = 0; k < 8; k++) {
        int p = tid + 512 * k;
        int c = p >> 6;
        int nl = p & 63;
        int n = n0 + nl;
        float lt = 0.f, s = 0.f;
        if (n < N_) {
            const float4* px = reinterpret_cast<const float4*>(
                x + ((size_t)(b * C_ + c) * N_ + n) * T_);
            float4 v0 = px[0], v1 = px[1], v2 = px[2];
            float xv[12] = {v0.x, v0.y, v0.z, v0.w,
                            v1.x, v1.y, v1.z, v1.w,
                            v2.x, v2.y, v2.z, v2.w};
#pragma unroll
            for (int t = 0; t < T_; t++) {
                lt = fmaf(xv[t], (float)t * (1.0f / 11.0f), lt);
                s += xv[t];
            }
        }
        slt[c * 64 + nl] = lt;
        srt[c * 64 + nl] = s - lt;    // t_dn = 1 - t_up
    }
    __syncthreads();

    // Phase 2a: threads 0..255 -> u, 256..511 -> v. Each thread: 2h x 4n.
    {
        const int t = tid & 255;
        const int mat = tid >> 8;
        const int ng2 = t & 15;       // n4 group
        const int h0 = (t >> 4) * 2;  // 0,2,..,30
        const float4* src = mat ? srt4 : slt4;
        const float* wsm = reinterpret_cast<const float*>(mat ? sW4 : sW3);
        float4* dst = mat ? sv4 : su4;

        float4 acc0 = {0,0,0,0}, acc1 = {0,0,0,0};
#pragma unroll 16
        for (int c = 0; c < 64; c++) {
            float4 l4 = src[c * 16 + ng2];
            float w0 = wsm[c * 32 + h0];
            float w1 = wsm[c * 32 + h0 + 1];
            acc0.x = fmaf(l4.x, w0, acc0.x); acc0.y = fmaf(l4.y, w0, acc0.y);
            acc0.z = fmaf(l4.z, w0, acc0.z); acc0.w = fmaf(l4.w, w0, acc0.w);
            acc1.x = fmaf(l4.x, w1, acc1.x); acc1.y = fmaf(l4.y, w1, acc1.y);
            acc1.z = fmaf(l4.z, w1, acc1.z); acc1.w = fmaf(l4.w, w1, acc1.w);
        }
        dst[h0 * 16 + ng2] = acc0;
        dst[(h0 + 1) * 16 + ng2] = acc1;
    }
    __syncthreads();

    // Phase 2b: threads 0..255 -> A, 256..511 -> Bv. Each thread: 4n x 4co.
    {
        const int t = tid & 255;
        const int mat = tid >> 8;
        const int cg = t & 15;        // co4 group
        const int ng = t >> 4;        // n4 group
        const float4* msm = mat ? scwT2 : scwT1;
        const float4* usm = mat ? sv4 : su4;

        float4 r0 = {0,0,0,0}, r1 = {0,0,0,0}, r2 = {0,0,0,0}, r3 = {0,0,0,0};
#pragma unroll 8
        for (int h = 0; h < 32; h++) {
            float4 m = msm[h * 16 + cg];
            float4 u4 = usm[h * 16 + ng];
            r0.x = fmaf(u4.x, m.x, r0.x); r0.y = fmaf(u4.x, m.y, r0.y);
            r0.z = fmaf(u4.x, m.z, r0.z); r0.w = fmaf(u4.x, m.w, r0.w);
            r1.x = fmaf(u4.y, m.x, r1.x); r1.y = fmaf(u4.y, m.y, r1.y);
            r1.z = fmaf(u4.y, m.z, r1.z); r1.w = fmaf(u4.y, m.w, r1.w);
            r2.x = fmaf(u4.z, m.x, r2.x); r2.y = fmaf(u4.z, m.y, r2.y);
            r2.z = fmaf(u4.z, m.z, r2.z); r2.w = fmaf(u4.z, m.w, r2.w);
            r3.x = fmaf(u4.w, m.x, r3.x); r3.y = fmaf(u4.w, m.y, r3.y);
            r3.z = fmaf(u4.w, m.z, r3.z); r3.w = fmaf(u4.w, m.w, r3.w);
        }

        uint2* gOut = reinterpret_cast<uint2*>(mat ? g_Bh : g_Ah);
        float4 cbv = {0,0,0,0};
        if (!mat) cbv = reinterpret_cast<const float4*>(conv_b)[cg];

        float4 rv[4] = {r0, r1, r2, r3};
#pragma unroll
        for (int i = 0; i < 4; i++) {
            int n = n0 + ng * 4 + i;
            if (n < N_) {
                float4 aa = rv[i];
                aa.x += cbv.x; aa.y += cbv.y; aa.z += cbv.z; aa.w += cbv.w;
                uint2 u;
                u.x = pack_half2(aa.x, aa.y);
                u.y = pack_half2(aa.z, aa.w);
                gOut[((size_t)b * N_ + n) * 16 + cg] = u;
            }
        }
    }
}

// ---------------------------------------------------------------------------
// Gather kernel: out[b,e,c] = A[b,idx[e],c] + Bv[b,idy[e],c]
// R7 structure (measured best: 30.4us) + 2-edge ILP per thread.
// Grid (E/64, 2 chalf, B), 256 threads; 8 threads/edge, uint2 (8B) loads.
// All 4 gathered loads issued before any consumption.
// ---------------------------------------------------------------------------
__global__ __launch_bounds__(256) void gather_add_kernel(const int* __restrict__ idx,
                                                         const int* __restrict__ idy,
                                                         float4* __restrict__ out) {
    const int tid = threadIdx.x;
    const int chalf = blockIdx.y;     // 0..1
    const int b = blockIdx.z;         // 0..7
    const int el = tid >> 3;          // 0..31
    const int q = tid & 7;            // uint2 within 64B half-row
    const int cq = chalf * 8 + q;
    const int e0 = blockIdx.x * 64 + el;
    const int e1 = e0 + 32;

    const int n1a = __ldg(idx + e0);
    const int n1b = __ldg(idx + e1);
    const int n2a = __ldg(idy + e0);
    const int n2b = __ldg(idy + e1);

    const uint2* __restrict__ A2 = reinterpret_cast<const uint2*>(g_Ah);
    const uint2* __restrict__ B2 = reinterpret_cast<const uint2*>(g_Bh);

    uint2 ua0 = __ldg(A2 + ((size_t)b * N_ + n1a) * 16 + cq);
    uint2 ub0 = __ldg(B2 + ((size_t)b * N_ + n2a) * 16 + cq);
    uint2 ua1 = __ldg(A2 + ((size_t)b * N_ + n1b) * 16 + cq);
    uint2 ub1 = __ldg(B2 + ((size_t)b * N_ + n2b) * 16 + cq);

    float2 a00 = __half22float2(*reinterpret_cast<__half2*>(&ua0.x));
    float2 a01 = __half22float2(*reinterpret_cast<__half2*>(&ua0.y));
    float2 v00 = __half22float2(*reinterpret_cast<__half2*>(&ub0.x));
    float2 v01 = __half22float2(*reinterpret_cast<__half2*>(&ub0.y));
    float2 a10 = __half22float2(*reinterpret_cast<__half2*>(&ua1.x));
    float2 a11 = __half22float2(*reinterpret_cast<__half2*>(&ua1.y));
    float2 v10 = __half22float2(*reinterpret_cast<__half2*>(&ub1.x));
    float2 v11 = __half22float2(*reinterpret_cast<__half2*>(&ub1.y));

    out[((size_t)b * E_ + e0) * 16 + cq] =
        make_float4(a00.x + v00.x, a00.y + v00.y, a01.x + v01.x, a01.y + v01.y);
    out[((size_t)b * E_ + e1) * 16 + cq] =
        make_float4(a10.x + v10.x, a10.y + v10.y, a11.x + v11.x, a11.y + v11.y);
}

// ---------------------------------------------------------------------------
// Launch. Inputs: x, idx, idy, W1_scale, W2_scale, W3, W4, conv_w, conv_b
// ---------------------------------------------------------------------------
extern "C" void kernel_launch(void* const* d_in, const int* in_sizes, int n_in,
                              void* d_out, int out_size) {
    const float* x   = (const float*)d_in[0];
    const int* idx   = (const int*)d_in[1];
    const int* idy   = (const int*)d_in[2];
    const float* s1  = (const float*)d_in[3];
    const float* s2  = (const float*)d_in[4];
    const float* W3  = (const float*)d_in[5];
    const float* W4  = (const float*)d_in[6];
    const float* cw  = (const float*)d_in[7];
    const float* cb  = (const float*)d_in[8];
    float4* out = (float4*)d_out;

    const int smem_bytes = 5120 * sizeof(float4);   // 80 KB
    cudaFuncSetAttribute(stage_AB_kernel,
                         cudaFuncAttributeMaxDynamicSharedMemorySize, smem_bytes);

    dim3 grd2((N_ + 63) / 64, B_);
    stage_AB_kernel<<<grd2, 512, smem_bytes>>>(x, W3, W4, cw, s1, s2, cb);

    dim3 grd3(E_ / 64, 2, B_);        // (1000, 2, 8) = 16000 blocks
    gather_add_kernel<<<grd3, 256>>>(idx, idy, out);
}

// round 12
// speedup vs baseline: 1.2776x; 1.0452x over previous
#include <cuda_runtime.h>
#include <cuda_fp16.h>
#include <cstdint>

// Problem shapes (fixed)
#define B_  8
#define C_  64
#define N_  2000
#define T_  12
#define E_  64000
#define HID_ 32

// Scratch
__device__ float g_M1[C_ * C_];            // M1[cin*64 + cout]
__device__ float g_M2[C_ * C_];
__device__ float g_lt[B_ * C_ * N_];       // [b][c][n]
__device__ float g_rt[B_ * C_ * N_];
// fp16 tables, flat layout [b][n][64c]; uint2 units: row stride 16.
__device__ __half g_Ah[B_ * N_ * C_];      // includes conv_b
__device__ __half g_Bh[B_ * N_ * C_];

__device__ __forceinline__ unsigned pack_half2(float a, float b) {
    __half2 h = __floats2half2_rn(a, b);
    return *reinterpret_cast<unsigned*>(&h);
}

// ---------------------------------------------------------------------------
// Kernel 1: fold. M1[cin][cout] = s1*sum_h W3[cin,h]*cw[cout,h];
//                 M2[cin][cout] = s2*sum_h W4[cin,h]*cw[cout,32+h].
// Grid 64 (one cin per block) x 128 threads (64 -> M1, 64 -> M2).
// Per thread: 8 contiguous float4 loads of cw + broadcast W row. ~1.5us.
// ---------------------------------------------------------------------------
__global__ __launch_bounds__(128) void fold_kernel(const float* __restrict__ W3,
                                                   const float* __restrict__ W4,
                                                   const float* __restrict__ cw,
                                                   const float* __restrict__ s1p,
                                                   const float* __restrict__ s2p) {
    const int cin = blockIdx.x;
    const int t = threadIdx.x;
    const int mat = t >> 6;
    const int cout = t & 63;

    const float* wrow = mat ? (W4 + cin * HID_) : (W3 + cin * HID_);
    const float sc = mat ? __ldg(s2p) : __ldg(s1p);
    const float4* cwp = reinterpret_cast<const float4*>(cw + cout * 64 + mat * 32);
    const float4* wp = reinterpret_cast<const float4*>(wrow);

    float acc = 0.f;
#pragma unroll
    for (int q = 0; q < 8; q++) {
        float4 w = __ldg(wp + q);
        float4 c = __ldg(cwp + q);
        acc = fmaf(w.x, c.x, acc);
        acc = fmaf(w.y, c.y, acc);
        acc = fmaf(w.z, c.z, acc);
        acc = fmaf(w.w, c.w, acc);
    }
    (mat ? g_M2 : g_M1)[cin * 64 + cout] = acc * sc;
}

// ---------------------------------------------------------------------------
// Kernel 2: time reduction, pure streaming. x -> lt/rt in [b][c][n].
// Grid (8 n-chunks, 64 c, 8 b) x 256 threads. No smem, no syncs.
// ---------------------------------------------------------------------------
__global__ __launch_bounds__(256) void reduce_kernel(const float* __restrict__ x) {
    const int n = blockIdx.x * 256 + threadIdx.x;
    const int c = blockIdx.y;
    const int b = blockIdx.z;
    if (n >= N_) return;

    const float4* px = reinterpret_cast<const float4*>(
        x + ((size_t)(b * C_ + c) * N_ + n) * T_);
    float4 v0 = __ldg(px), v1 = __ldg(px + 1), v2 = __ldg(px + 2);
    float xv[12] = {v0.x, v0.y, v0.z, v0.w,
                    v1.x, v1.y, v1.z, v1.w,
                    v2.x, v2.y, v2.z, v2.w};
    float lt = 0.f, s = 0.f;
#pragma unroll
    for (int t = 0; t < T_; t++) {
        lt = fmaf(xv[t], (float)t * (1.0f / 11.0f), lt);
        s += xv[t];
    }
    const size_t o = (size_t)(b * C_ + c) * N_ + n;
    g_lt[o] = lt;
    g_rt[o] = s - lt;    // t_dn = 1 - t_up
}

// ---------------------------------------------------------------------------
// Kernel 3: project. A[b,n,:] = lt[b,:,n]@M1 + cb; Bv = rt[b,:,n]@M2. fp16 out.
// Grid (32 n-tiles, 8 b) x 256 threads, 64 KB dynamic smem (3 blocks/SM).
// R3-proven register tiling: 4n x 4co x 2 mats, 1 B LDS per MAC.
// ---------------------------------------------------------------------------
__global__ __launch_bounds__(256) void project_kernel(const float* __restrict__ conv_b) {
    extern __shared__ float4 sm[];
    float4* sM1  = sm;            // [c][co4]  64*16 = 1024 f4 (16 KB)
    float4* sM2  = sm + 1024;     // 16 KB
    float4* slt4 = sm + 2048;     // [c][n4]   16 KB
    float4* srt4 = sm + 3072;     // 16 KB
    float* sltf = reinterpret_cast<float*>(slt4);
    float* srtf = reinterpret_cast<float*>(srt4);

    const int tid = threadIdx.x;
    const int b = blockIdx.y;
    const int n0 = blockIdx.x * 64;

    // Load M1/M2 (coalesced f4 copies)
    {
        const float4* m1g = reinterpret_cast<const float4*>(g_M1);
        const float4* m2g = reinterpret_cast<const float4*>(g_M2);
#pragma unroll
        for (int k = 0; k < 4; k++) {
            int i = tid + 256 * k;
            sM1[i] = m1g[i];
            sM2[i] = m2g[i];
        }
    }

    // Load lt/rt tile: slt[c][nl] = g_lt[b][c][n0+nl]
#pragma unroll
    for (int k = 0; k < 16; k++) {
        int i = tid + 256 * k;
        int c = i >> 6;
        int nl = i & 63;
        int n = n0 + nl;
        float lv = 0.f, rv = 0.f;
        if (n < N_) {
            size_t o = (size_t)(b * C_ + c) * N_ + n;
            lv = __ldg(g_lt + o);
            rv = __ldg(g_rt + o);
        }
        sltf[i] = lv;
        srtf[i] = rv;
    }
    __syncthreads();

    const int cg = tid & 15;          // co4 group
    const int ng = tid >> 4;          // n4 group

    float4 a0 = {0,0,0,0}, a1 = {0,0,0,0}, a2 = {0,0,0,0}, a3 = {0,0,0,0};
    float4 b0 = {0,0,0,0}, b1 = {0,0,0,0}, b2 = {0,0,0,0}, b3 = {0,0,0,0};

#pragma unroll 16
    for (int c = 0; c < 64; c++) {
        float4 m1 = sM1[c * 16 + cg];
        float4 m2 = sM2[c * 16 + cg];
        float4 l = slt4[c * 16 + ng];
        float4 r = srt4[c * 16 + ng];

        a0.x = fmaf(l.x, m1.x, a0.x); a0.y = fmaf(l.x, m1.y, a0.y);
        a0.z = fmaf(l.x, m1.z, a0.z); a0.w = fmaf(l.x, m1.w, a0.w);
        a1.x = fmaf(l.y, m1.x, a1.x); a1.y = fmaf(l.y, m1.y, a1.y);
        a1.z = fmaf(l.y, m1.z, a1.z); a1.w = fmaf(l.y, m1.w, a1.w);
        a2.x = fmaf(l.z, m1.x, a2.x); a2.y = fmaf(l.z, m1.y, a2.y);
        a2.z = fmaf(l.z, m1.z, a2.z); a2.w = fmaf(l.z, m1.w, a2.w);
        a3.x = fmaf(l.w, m1.x, a3.x); a3.y = fmaf(l.w, m1.y, a3.y);
        a3.z = fmaf(l.w, m1.z, a3.z); a3.w = fmaf(l.w, m1.w, a3.w);

        b0.x = fmaf(r.x, m2.x, b0.x); b0.y = fmaf(r.x, m2.y, b0.y);
        b0.z = fmaf(r.x, m2.z, b0.z); b0.w = fmaf(r.x, m2.w, b0.w);
        b1.x = fmaf(r.y, m2.x, b1.x); b1.y = fmaf(r.y, m2.y, b1.y);
        b1.z = fmaf(r.y, m2.z, b1.z); b1.w = fmaf(r.y, m2.w, b1.w);
        b2.x = fmaf(r.z, m2.x, b2.x); b2.y = fmaf(r.z, m2.y, b2.y);
        b2.z = fmaf(r.z, m2.z, b2.z); b2.w = fmaf(r.z, m2.w, b2.w);
        b3.x = fmaf(r.w, m2.x, b3.x); b3.y = fmaf(r.w, m2.y, b3.y);
        b3.z = fmaf(r.w, m2.z, b3.z); b3.w = fmaf(r.w, m2.w, b3.w);
    }

    float4 cbv = reinterpret_cast<const float4*>(conv_b)[cg];
    uint2* gA2 = reinterpret_cast<uint2*>(g_Ah);
    uint2* gB2 = reinterpret_cast<uint2*>(g_Bh);

    float4 av[4] = {a0, a1, a2, a3};
    float4 bv[4] = {b0, b1, b2, b3};
#pragma unroll
    for (int i = 0; i < 4; i++) {
        int n = n0 + ng * 4 + i;
        if (n < N_) {
            size_t o = ((size_t)b * N_ + n) * 16 + cg;
            float4 aa = av[i];
            aa.x += cbv.x; aa.y += cbv.y; aa.z += cbv.z; aa.w += cbv.w;
            uint2 ua, ub;
            ua.x = pack_half2(aa.x, aa.y);
            ua.y = pack_half2(aa.z, aa.w);
            ub.x = pack_half2(bv[i].x, bv[i].y);
            ub.y = pack_half2(bv[i].z, bv[i].w);
            gA2[o] = ua;
            gB2[o] = ub;
        }
    }
}

// ---------------------------------------------------------------------------
// Kernel 4: gather (unchanged from R11 measured-best: 27.4us).
// Grid (E/64, 2 chalf, B), 256 threads; 8 thr/edge, uint2 loads, 2-edge ILP.
// ---------------------------------------------------------------------------
__global__ __launch_bounds__(256) void gather_add_kernel(const int* __restrict__ idx,
                                                         const int* __restrict__ idy,
                                                         float4* __restrict__ out) {
    const int tid = threadIdx.x;
    const int chalf = blockIdx.y;     // 0..1
    const int b = blockIdx.z;         // 0..7
    const int el = tid >> 3;          // 0..31
    const int q = tid & 7;            // uint2 within 64B half-row
    const int cq = chalf * 8 + q;
    const int e0 = blockIdx.x * 64 + el;
    const int e1 = e0 + 32;

    const int n1a = __ldg(idx + e0);
    const int n1b = __ldg(idx + e1);
    const int n2a = __ldg(idy + e0);
    const int n2b = __ldg(idy + e1);

    const uint2* __restrict__ A2 = reinterpret_cast<const uint2*>(g_Ah);
    const uint2* __restrict__ B2 = reinterpret_cast<const uint2*>(g_Bh);

    uint2 ua0 = __ldg(A2 + ((size_t)b * N_ + n1a) * 16 + cq);
    uint2 ub0 = __ldg(B2 + ((size_t)b * N_ + n2a) * 16 + cq);
    uint2 ua1 = __ldg(A2 + ((size_t)b * N_ + n1b) * 16 + cq);
    uint2 ub1 = __ldg(B2 + ((size_t)b * N_ + n2b) * 16 + cq);

    float2 a00 = __half22float2(*reinterpret_cast<__half2*>(&ua0.x));
    float2 a01 = __half22float2(*reinterpret_cast<__half2*>(&ua0.y));
    float2 v00 = __half22float2(*reinterpret_cast<__half2*>(&ub0.x));
    float2 v01 = __half22float2(*reinterpret_cast<__half2*>(&ub0.y));
    float2 a10 = __half22float2(*reinterpret_cast<__half2*>(&ua1.x));
    float2 a11 = __half22float2(*reinterpret_cast<__half2*>(&ua1.y));
    float2 v10 = __half22float2(*reinterpret_cast<__half2*>(&ub1.x));
    float2 v11 = __half22float2(*reinterpret_cast<__half2*>(&ub1.y));

    out[((size_t)b * E_ + e0) * 16 + cq] =
        make_float4(a00.x + v00.x, a00.y + v00.y, a01.x + v01.x, a01.y + v01.y);
    out[((size_t)b * E_ + e1) * 16 + cq] =
        make_float4(a10.x + v10.x, a10.y + v10.y, a11.x + v11.x, a11.y + v11.y);
}

// ---------------------------------------------------------------------------
// Launch. Inputs: x, idx, idy, W1_scale, W2_scale, W3, W4, conv_w, conv_b
// ---------------------------------------------------------------------------
extern "C" void kernel_launch(void* const* d_in, const int* in_sizes, int n_in,
                              void* d_out, int out_size) {
    const float* x   = (const float*)d_in[0];
    const int* idx   = (const int*)d_in[1];
    const int* idy   = (const int*)d_in[2];
    const float* s1  = (const float*)d_in[3];
    const float* s2  = (const float*)d_in[4];
    const float* W3  = (const float*)d_in[5];
    const float* W4  = (const float*)d_in[6];
    const float* cw  = (const float*)d_in[7];
    const float* cb  = (const float*)d_in[8];
    float4* out = (float4*)d_out;

    fold_kernel<<<64, 128>>>(W3, W4, cw, s1, s2);

    dim3 grdR(8, 64, 8);
    reduce_kernel<<<grdR, 256>>>(x);

    const int smem_bytes = 4096 * sizeof(float4);   // 64 KB
    cudaFuncSetAttribute(project_kernel,
                         cudaFuncAttributeMaxDynamicSharedMemorySize, smem_bytes);
    dim3 grdP(32, 8);
    project_kernel<<<grdP, 256, smem_bytes>>>(cb);

    dim3 grdG(E_ / 64, 2, B_);        // (1000, 2, 8)
    gather_add_kernel<<<grdG, 256>>>(idx, idy, out);
}